// round 3
// baseline (speedup 1.0000x reference)
#include <cuda_runtime.h>
#include <math_constants.h>

// Problem constants
#define NUM_VARS 64
#define KK       32
#define NUM_CATS 256
#define NUM_INPUT (NUM_VARS * KK)   // 2048
#define LL       4
#define EE       16384
#define NN       8192
#define CC       4
#define BB       1024
#define B4       (BB / 4)           // 256 float4 per row
#define TOTAL_NODES (NUM_INPUT + LL * NN)  // 34816
#define NCHUNK   32                 // root reduction chunks
#define BCHUNKS  2                  // batch tiles for L2 residency
#define B4C      (B4 / BCHUNKS)     // float4 cols per batch tile (128)
#define NPT      2                  // nodes per thread in layer kernel
#define HALF_N   (NN / NPT)         // 4096

// Scratch: node-marginal pool (142.6 MB), root partials, resolved pair indices
__device__ float g_node_mars[(size_t)TOTAL_NODES * BB];
__device__ float g_partial[NCHUNK * BB];
__device__ int2  g_pairs[LL * NN * CC];   // (l,n,c) -> (p0,p1) resolved product pair

// ---------------------------------------------------------------------------
// Kernel 0 (fused): blocks 0..63 do the input layer; blocks 64.. resolve the
// ch_ids -> prod_ids indirection. The two jobs are independent.
// ---------------------------------------------------------------------------
__global__ void prep_kernel(const int* __restrict__ inputs,
                            const float* __restrict__ input_logp,
                            const int* __restrict__ sum_ch_ids,
                            const int2* __restrict__ prod_ids) {
    if (blockIdx.x < NUM_VARS) {
        // --- input layer: node_mars[v*K+k, b] = input_logp[v, k, inputs[b,v]]
        __shared__ int cats[BB];
        const int v = blockIdx.x;
        for (int b = threadIdx.x; b < BB; b += blockDim.x)
            cats[b] = inputs[b * NUM_VARS + v];
        __syncthreads();

        const float* lp = input_logp + (size_t)v * KK * NUM_CATS;
        float* out = g_node_mars + (size_t)v * KK * BB;
        for (int i = threadIdx.x; i < KK * BB; i += blockDim.x) {
            const int k = i >> 10;
            const int b = i & (BB - 1);
            out[i] = __ldg(lp + k * NUM_CATS + cats[b]);
        }
    } else {
        // --- resolve: g_pairs[l,n,c] = prod_ids[l, sum_ch_ids[l,n,c]]
        const int idx = (blockIdx.x - NUM_VARS) * blockDim.x + threadIdx.x;  // over L*N*C
        const int l = idx / (NN * CC);
        const int e = __ldg(sum_ch_ids + idx);
        g_pairs[idx] = __ldg(prod_ids + (size_t)l * EE + e);
    }
}

// ---------------------------------------------------------------------------
// Layer kernel: 2 sum nodes per thread (n, n+4096) -> 16 independent gathers
// in flight. Product layer fused; indirection pre-resolved; batch-tiled.
// ---------------------------------------------------------------------------
__device__ __forceinline__ float lse4(float a, float b, float c, float d) {
    float m = fmaxf(fmaxf(a, b), fmaxf(c, d));
    float s = __expf(a - m) + __expf(b - m) + __expf(c - m) + __expf(d - m);
    return m + __logf(s);
}

__device__ __forceinline__ float4 lse4v(const float4& x0, const float4& x1,
                                        const float4& x2, const float4& x3) {
    float4 o;
    o.x = lse4(x0.x, x1.x, x2.x, x3.x);
    o.y = lse4(x0.y, x1.y, x2.y, x3.y);
    o.z = lse4(x0.z, x1.z, x2.z, x3.z);
    o.w = lse4(x0.w, x1.w, x2.w, x3.w);
    return o;
}

__device__ __forceinline__ void addw(float4& d, const float4& a, const float4& b, float w) {
    d.x = a.x + b.x + w; d.y = a.y + b.y + w; d.z = a.z + b.z + w; d.w = a.w + b.w + w;
}

__global__ void __launch_bounds__(B4C)
layer_kernel(const float4* __restrict__ logw,  // N entries (this layer)
             int l, int out_base, int bc) {
    const int n0 = blockIdx.x;            // node A
    const int n1 = blockIdx.x + HALF_N;   // node B
    const int b4 = bc * B4C + threadIdx.x;

    const int4* prbase = reinterpret_cast<const int4*>(g_pairs) + (size_t)l * NN * 2;
    const int4 pa0 = __ldg(prbase + n0 * 2);
    const int4 pb0 = __ldg(prbase + n0 * 2 + 1);
    const int4 pa1 = __ldg(prbase + n1 * 2);
    const int4 pb1 = __ldg(prbase + n1 * 2 + 1);
    const float4 w0 = __ldg(logw + n0);
    const float4 w1 = __ldg(logw + n1);

    const float4* nm = reinterpret_cast<const float4*>(g_node_mars);

    // 16 independent gathers — maximize memory-level parallelism
    const float4 a00 = __ldg(nm + (size_t)pa0.x * B4 + b4);
    const float4 c00 = __ldg(nm + (size_t)pa0.y * B4 + b4);
    const float4 a01 = __ldg(nm + (size_t)pa0.z * B4 + b4);
    const float4 c01 = __ldg(nm + (size_t)pa0.w * B4 + b4);
    const float4 a02 = __ldg(nm + (size_t)pb0.x * B4 + b4);
    const float4 c02 = __ldg(nm + (size_t)pb0.y * B4 + b4);
    const float4 a03 = __ldg(nm + (size_t)pb0.z * B4 + b4);
    const float4 c03 = __ldg(nm + (size_t)pb0.w * B4 + b4);
    const float4 a10 = __ldg(nm + (size_t)pa1.x * B4 + b4);
    const float4 c10 = __ldg(nm + (size_t)pa1.y * B4 + b4);
    const float4 a11 = __ldg(nm + (size_t)pa1.z * B4 + b4);
    const float4 c11 = __ldg(nm + (size_t)pa1.w * B4 + b4);
    const float4 a12 = __ldg(nm + (size_t)pb1.x * B4 + b4);
    const float4 c12 = __ldg(nm + (size_t)pb1.y * B4 + b4);
    const float4 a13 = __ldg(nm + (size_t)pb1.z * B4 + b4);
    const float4 c13 = __ldg(nm + (size_t)pb1.w * B4 + b4);

    float4* nmo = reinterpret_cast<float4*>(g_node_mars);

    // node A
    {
        float4 x0, x1, x2, x3;
        addw(x0, a00, c00, w0.x);
        addw(x1, a01, c01, w0.y);
        addw(x2, a02, c02, w0.z);
        addw(x3, a03, c03, w0.w);
        nmo[(size_t)(out_base + n0) * B4 + b4] = lse4v(x0, x1, x2, x3);
    }
    // node B
    {
        float4 x0, x1, x2, x3;
        addw(x0, a10, c10, w1.x);
        addw(x1, a11, c11, w1.y);
        addw(x2, a12, c12, w1.z);
        addw(x3, a13, c13, w1.w);
        nmo[(size_t)(out_base + n1) * B4 + b4] = lse4v(x0, x1, x2, x3);
    }
}

// ---------------------------------------------------------------------------
// Root partial logsumexp + final combine.
// ---------------------------------------------------------------------------
__global__ void root_partial_kernel(const float* __restrict__ root_logw) {
    const int chunk = blockIdx.x;
    const int b = blockIdx.y * blockDim.x + threadIdx.x;
    const float* last = g_node_mars + (size_t)(NUM_INPUT + (LL - 1) * NN) * BB;
    const int n0 = chunk * (NN / NCHUNK);

    float m = -CUDART_INF_F, s = 0.f;
#pragma unroll 4
    for (int i = 0; i < NN / NCHUNK; i++) {
        const int n = n0 + i;
        const float x = __ldg(root_logw + n) + last[(size_t)n * BB + b];
        if (x > m) { s = s * __expf(m - x) + 1.f; m = x; }
        else       { s += __expf(x - m); }
    }
    g_partial[chunk * BB + b] = m + __logf(s);
}

__global__ void root_final_kernel(float* __restrict__ out) {
    const int b = blockIdx.x * blockDim.x + threadIdx.x;
    float m = -CUDART_INF_F, s = 0.f;
#pragma unroll
    for (int c = 0; c < NCHUNK; c++) {
        const float x = g_partial[c * BB + b];
        if (x > m) { s = s * __expf(m - x) + 1.f; m = x; }
        else       { s += __expf(x - m); }
    }
    out[b] = m + __logf(s);
}

// ---------------------------------------------------------------------------
extern "C" void kernel_launch(void* const* d_in, const int* in_sizes, int n_in,
                              void* d_out, int out_size) {
    const int*   inputs     = (const int*)  d_in[0];
    const float* input_logp = (const float*)d_in[1];
    const int*   prod_ids   = (const int*)  d_in[2];  // (L, E, 2)
    const int*   sum_ch_ids = (const int*)  d_in[3];  // (L, N, C)
    const float* sum_logw   = (const float*)d_in[4];  // (L, N, C)
    const float* root_logw  = (const float*)d_in[5];  // (N,)
    float* out = (float*)d_out;

    // input layer (64 blocks) + indirection resolve (512 blocks), fused
    prep_kernel<<<NUM_VARS + (LL * NN * CC) / 256, 256>>>(
        inputs, input_logp, sum_ch_ids,
        reinterpret_cast<const int2*>(prod_ids));

    // Batch-tiled layer sweep: each tile's working set stays L2-resident
    for (int bc = 0; bc < BCHUNKS; bc++) {
        for (int l = 0; l < LL; l++) {
            const float4* lw = reinterpret_cast<const float4*>(sum_logw + (size_t)l * NN * CC);
            layer_kernel<<<HALF_N, B4C>>>(lw, l, NUM_INPUT + l * NN, bc);
        }
    }

    dim3 rp_grid(NCHUNK, BB / 256);
    root_partial_kernel<<<rp_grid, 256>>>(root_logw);
    root_final_kernel<<<BB / 256, 256>>>(out);
}

// round 4
// speedup vs baseline: 1.2964x; 1.2964x over previous
#include <cuda_runtime.h>
#include <math_constants.h>

// Problem constants
#define NUM_VARS 64
#define KK       32
#define NUM_CATS 256
#define NUM_INPUT (NUM_VARS * KK)   // 2048
#define LL       4
#define EE       16384
#define NN       8192
#define CC       4
#define BB       1024
#define B4       (BB / 4)           // 256 float4 per row
#define TOTAL_NODES (NUM_INPUT + LL * NN)  // 34816
#define NCHUNK   64                 // root reduction chunks (chain length 128)

#define GRID_BLOCKS 592             // 4 blocks/SM on 148 SMs — co-resident
#define THREADS     256
#define NTHREADS    (GRID_BLOCKS * THREADS)

// Scratch: node-marginal pool (142.6 MB), root partials, resolved pair indices
__device__ float g_node_mars[(size_t)TOTAL_NODES * BB];
__device__ float g_partial[NCHUNK * BB];
__device__ int2  g_pairs[LL * NN * CC];   // (l,n,c) -> (p0,p1)

// Grid barrier state (returns to count=0 at end of every run; gen monotonic)
__device__ unsigned g_bar_count;
__device__ volatile unsigned g_bar_gen;

__device__ __forceinline__ void grid_sync() {
    __syncthreads();
    if (threadIdx.x == 0) {
        __threadfence();                      // release: flush my SM's writes
        unsigned gen = g_bar_gen;
        if (atomicAdd(&g_bar_count, 1u) == GRID_BLOCKS - 1u) {
            g_bar_count = 0;
            __threadfence();
            g_bar_gen = gen + 1u;
        } else {
            while (g_bar_gen == gen) { }
        }
    }
    __syncthreads();
    __threadfence();                          // acquire: invalidate L1D before reads
}

__device__ __forceinline__ float lse4(float a, float b, float c, float d) {
    float m = fmaxf(fmaxf(a, b), fmaxf(c, d));
    float s = __expf(a - m) + __expf(b - m) + __expf(c - m) + __expf(d - m);
    return m + __logf(s);
}

__global__ void __launch_bounds__(THREADS, 4)
circuit_kernel(const int* __restrict__ inputs,
               const float* __restrict__ input_logp,
               const int2* __restrict__ prod_ids,     // (L, E)
               const int* __restrict__ sum_ch_ids,    // (L, N, C)
               const float4* __restrict__ sum_logw,   // (L, N) as float4
               const float* __restrict__ root_logw,   // (N,)
               float* __restrict__ out) {
    const int gtid = blockIdx.x * THREADS + threadIdx.x;

    // ---------------- Phase 0: input layer + indirection resolve ----------------
    // input: node_mars[v*K+k, b] = input_logp[v, k, inputs[b, v]]
    for (int idx = gtid; idx < NUM_INPUT * BB; idx += NTHREADS) {
        const int v = idx >> 15;            // / (K*B)
        const int k = (idx >> 10) & (KK - 1);
        const int b = idx & (BB - 1);
        const int cat = __ldg(inputs + b * NUM_VARS + v);
        g_node_mars[idx] = __ldg(input_logp + ((v * KK + k) << 8) + cat);
    }
    // resolve: g_pairs[l,n,c] = prod_ids[l, sum_ch_ids[l,n,c]]
    for (int idx = gtid; idx < LL * NN * CC; idx += NTHREADS) {
        const int l = idx / (NN * CC);
        const int e = __ldg(sum_ch_ids + idx);
        g_pairs[idx] = __ldg(prod_ids + (size_t)l * EE + e);
    }
    grid_sync();

    // ---------------- Phases 1..4: sum layers (product fused) ----------------
    const float4* nm = reinterpret_cast<const float4*>(g_node_mars);
    float4* nmo = reinterpret_cast<float4*>(g_node_mars);
    const int b4 = threadIdx.x;   // float4 column 0..255 (full batch)

    for (int l = 0; l < LL; l++) {
        const int out_base = NUM_INPUT + l * NN;
        const int4* prbase = reinterpret_cast<const int4*>(g_pairs) + (size_t)l * NN * 2;
        const float4* lw = sum_logw + (size_t)l * NN;

        for (int n = blockIdx.x; n < NN; n += GRID_BLOCKS) {
            const int4 pa = __ldg(prbase + n * 2);      // {p0_0,p1_0,p0_1,p1_1}
            const int4 pb = __ldg(prbase + n * 2 + 1);  // {p0_2,p1_2,p0_3,p1_3}
            const float4 w = __ldg(lw + n);

            const float4 a0 = __ldg(nm + (size_t)pa.x * B4 + b4);
            const float4 c0 = __ldg(nm + (size_t)pa.y * B4 + b4);
            const float4 a1 = __ldg(nm + (size_t)pa.z * B4 + b4);
            const float4 c1 = __ldg(nm + (size_t)pa.w * B4 + b4);
            const float4 a2 = __ldg(nm + (size_t)pb.x * B4 + b4);
            const float4 c2 = __ldg(nm + (size_t)pb.y * B4 + b4);
            const float4 a3 = __ldg(nm + (size_t)pb.z * B4 + b4);
            const float4 c3 = __ldg(nm + (size_t)pb.w * B4 + b4);

            float4 x0, x1, x2, x3, o;
            x0.x = a0.x + c0.x + w.x; x0.y = a0.y + c0.y + w.x; x0.z = a0.z + c0.z + w.x; x0.w = a0.w + c0.w + w.x;
            x1.x = a1.x + c1.x + w.y; x1.y = a1.y + c1.y + w.y; x1.z = a1.z + c1.z + w.y; x1.w = a1.w + c1.w + w.y;
            x2.x = a2.x + c2.x + w.z; x2.y = a2.y + c2.y + w.z; x2.z = a2.z + c2.z + w.z; x2.w = a2.w + c2.w + w.z;
            x3.x = a3.x + c3.x + w.w; x3.y = a3.y + c3.y + w.w; x3.z = a3.z + c3.z + w.w; x3.w = a3.w + c3.w + w.w;

            o.x = lse4(x0.x, x1.x, x2.x, x3.x);
            o.y = lse4(x0.y, x1.y, x2.y, x3.y);
            o.z = lse4(x0.z, x1.z, x2.z, x3.z);
            o.w = lse4(x0.w, x1.w, x2.w, x3.w);

            nmo[(size_t)(out_base + n) * B4 + b4] = o;
        }
        grid_sync();
    }

    // ---------------- Phase 5: root partial logsumexp ----------------
    // item = (chunk, b): online LSE over 128 nodes
    {
        const float* last = g_node_mars + (size_t)(NUM_INPUT + (LL - 1) * NN) * BB;
        const int idx = gtid;
        if (idx < NCHUNK * BB) {
            const int chunk = idx >> 10;
            const int b = idx & (BB - 1);
            const int n0 = chunk * (NN / NCHUNK);
            float m = -CUDART_INF_F, s = 0.f;
#pragma unroll 4
            for (int i = 0; i < NN / NCHUNK; i++) {
                const int n = n0 + i;
                const float x = __ldg(root_logw + n) + last[(size_t)n * BB + b];
                const float mn = fmaxf(m, x);
                s = s * __expf(m - mn) + __expf(x - mn);
                m = mn;
            }
            g_partial[chunk * BB + b] = m + __logf(s);
        }
    }
    grid_sync();

    // ---------------- Phase 6: final combine (warp per column) ----------------
    {
        const int wgid = gtid >> 5;
        const int lane = gtid & 31;
        if (wgid < BB) {
            const int b = wgid;
            const float x0 = g_partial[lane * BB + b];
            const float x1 = g_partial[(lane + 32) * BB + b];
            float m = fmaxf(x0, x1);
#pragma unroll
            for (int o = 16; o > 0; o >>= 1)
                m = fmaxf(m, __shfl_xor_sync(0xFFFFFFFF, m, o));
            float s = __expf(x0 - m) + __expf(x1 - m);
#pragma unroll
            for (int o = 16; o > 0; o >>= 1)
                s += __shfl_xor_sync(0xFFFFFFFF, s, o);
            if (lane == 0) out[b] = m + __logf(s);
        }
    }
}

// ---------------------------------------------------------------------------
extern "C" void kernel_launch(void* const* d_in, const int* in_sizes, int n_in,
                              void* d_out, int out_size) {
    const int*   inputs     = (const int*)  d_in[0];
    const float* input_logp = (const float*)d_in[1];
    const int*   prod_ids   = (const int*)  d_in[2];  // (L, E, 2)
    const int*   sum_ch_ids = (const int*)  d_in[3];  // (L, N, C)
    const float* sum_logw   = (const float*)d_in[4];  // (L, N, C)
    const float* root_logw  = (const float*)d_in[5];  // (N,)
    float* out = (float*)d_out;

    circuit_kernel<<<GRID_BLOCKS, THREADS>>>(
        inputs, input_logp,
        reinterpret_cast<const int2*>(prod_ids),
        sum_ch_ids,
        reinterpret_cast<const float4*>(sum_logw),
        root_logw, out);
}

// round 5
// speedup vs baseline: 1.4400x; 1.1108x over previous
#include <cuda_runtime.h>
#include <math_constants.h>

// Problem constants
#define NUM_VARS 64
#define KK       32
#define NUM_CATS 256
#define NUM_INPUT (NUM_VARS * KK)   // 2048
#define LL       4
#define EE       16384
#define NN       8192
#define CC       4
#define BB       1024
#define B4       (BB / 4)           // 256 float4 per row
#define TOTAL_NODES (NUM_INPUT + LL * NN)  // 34816
#define NCHUNK   64                 // root reduction chunks (chain length 128)

#define GRID_BLOCKS 740             // 5 blocks/SM on 148 SMs — co-resident
#define THREADS     256
#define NTHREADS    (GRID_BLOCKS * THREADS)

#define LOG2E 1.4426950408889634f
#define LN2   0.6931471805599453f

// Scratch: node-marginal pool in LOG2 domain (142.6 MB), root partials, pairs
__device__ float g_node_mars[(size_t)TOTAL_NODES * BB];
__device__ float g_partial[NCHUNK * BB];
__device__ int2  g_pairs[LL * NN * CC];   // (l,n,c) -> (p0,p1)

// Grid barrier state
__device__ unsigned g_bar_count;
__device__ volatile unsigned g_bar_gen;

__device__ __forceinline__ void grid_sync() {
    __syncthreads();
    if (threadIdx.x == 0) {
        __threadfence();                      // release
        unsigned gen = g_bar_gen;
        if (atomicAdd(&g_bar_count, 1u) == GRID_BLOCKS - 1u) {
            g_bar_count = 0;
            __threadfence();
            g_bar_gen = gen + 1u;
        } else {
            while (g_bar_gen == gen) { }
        }
    }
    __syncthreads();
    __threadfence();                          // acquire
}

__device__ __forceinline__ float ex2(float x) {
    float r; asm("ex2.approx.ftz.f32 %0, %1;" : "=f"(r) : "f"(x)); return r;
}
__device__ __forceinline__ float lg2(float x) {
    float r; asm("lg2.approx.ftz.f32 %0, %1;" : "=f"(r) : "f"(x)); return r;
}

// base-2 logsumexp of 4
__device__ __forceinline__ float lse4_2(float a, float b, float c, float d) {
    float m = fmaxf(fmaxf(a, b), fmaxf(c, d));
    float s = ex2(a - m) + ex2(b - m) + ex2(c - m) + ex2(d - m);
    return m + lg2(s);
}

__global__ void __launch_bounds__(THREADS, 5)
circuit_kernel(const int* __restrict__ inputs,
               const float* __restrict__ input_logp,
               const int2* __restrict__ prod_ids,     // (L, E)
               const int* __restrict__ sum_ch_ids,    // (L, N, C)
               const float4* __restrict__ sum_logw,   // (L, N) as float4
               const float* __restrict__ root_logw,   // (N,)
               float* __restrict__ out) {
    const int gtid = blockIdx.x * THREADS + threadIdx.x;

    // ---------------- Phase 0: input layer (-> log2 domain) + resolve ----------
    for (int idx = gtid; idx < NUM_INPUT * BB; idx += NTHREADS) {
        const int v = idx >> 15;
        const int k = (idx >> 10) & (KK - 1);
        const int b = idx & (BB - 1);
        const int cat = __ldg(inputs + b * NUM_VARS + v);
        g_node_mars[idx] = __ldg(input_logp + ((v * KK + k) << 8) + cat) * LOG2E;
    }
    for (int idx = gtid; idx < LL * NN * CC; idx += NTHREADS) {
        const int l = idx / (NN * CC);
        const int e = __ldg(sum_ch_ids + idx);
        g_pairs[idx] = __ldg(prod_ids + (size_t)l * EE + e);
    }
    grid_sync();

    // ---------------- Phases 1..4: sum layers (product fused, log2 domain) -----
    const float4* nm = reinterpret_cast<const float4*>(g_node_mars);
    float4* nmo = reinterpret_cast<float4*>(g_node_mars);
    const unsigned b4 = threadIdx.x;   // float4 column 0..255

    for (int l = 0; l < LL; l++) {
        const int out_base = NUM_INPUT + l * NN;
        const int4* prbase = reinterpret_cast<const int4*>(g_pairs) + (size_t)l * NN * 2;
        const float4* lw = sum_logw + (size_t)l * NN;

        for (int n = blockIdx.x; n < NN; n += GRID_BLOCKS) {
            const int4 pa = __ldg(prbase + n * 2);
            const int4 pb = __ldg(prbase + n * 2 + 1);
            const float4 w = __ldg(lw + n);
            const float w0 = w.x * LOG2E, w1 = w.y * LOG2E;
            const float w2 = w.z * LOG2E, w3 = w.w * LOG2E;

            // 32-bit float4-offsets (max 8.9M < 2^32) — halves address regs
            const unsigned o0 = (unsigned)pa.x * B4 + b4;
            const unsigned o1 = (unsigned)pa.y * B4 + b4;
            const unsigned o2 = (unsigned)pa.z * B4 + b4;
            const unsigned o3 = (unsigned)pa.w * B4 + b4;
            const unsigned o4 = (unsigned)pb.x * B4 + b4;
            const unsigned o5 = (unsigned)pb.y * B4 + b4;
            const unsigned o6 = (unsigned)pb.z * B4 + b4;
            const unsigned o7 = (unsigned)pb.w * B4 + b4;

            const float4 a0 = __ldg(nm + o0);
            const float4 c0 = __ldg(nm + o1);
            const float4 a1 = __ldg(nm + o2);
            const float4 c1 = __ldg(nm + o3);
            const float4 a2 = __ldg(nm + o4);
            const float4 c2 = __ldg(nm + o5);
            const float4 a3 = __ldg(nm + o6);
            const float4 c3 = __ldg(nm + o7);

            float4 x0, x1, x2, x3, o;
            x0.x = a0.x + c0.x + w0; x0.y = a0.y + c0.y + w0; x0.z = a0.z + c0.z + w0; x0.w = a0.w + c0.w + w0;
            x1.x = a1.x + c1.x + w1; x1.y = a1.y + c1.y + w1; x1.z = a1.z + c1.z + w1; x1.w = a1.w + c1.w + w1;
            x2.x = a2.x + c2.x + w2; x2.y = a2.y + c2.y + w2; x2.z = a2.z + c2.z + w2; x2.w = a2.w + c2.w + w2;
            x3.x = a3.x + c3.x + w3; x3.y = a3.y + c3.y + w3; x3.z = a3.z + c3.z + w3; x3.w = a3.w + c3.w + w3;

            o.x = lse4_2(x0.x, x1.x, x2.x, x3.x);
            o.y = lse4_2(x0.y, x1.y, x2.y, x3.y);
            o.z = lse4_2(x0.z, x1.z, x2.z, x3.z);
            o.w = lse4_2(x0.w, x1.w, x2.w, x3.w);

            nmo[(size_t)(out_base + n) * B4 + b4] = o;
        }
        grid_sync();
    }

    // ---------------- Phase 5: root partial logsumexp (base 2) ----------------
    {
        const float* last = g_node_mars + (size_t)(NUM_INPUT + (LL - 1) * NN) * BB;
        const int idx = gtid;
        if (idx < NCHUNK * BB) {
            const int chunk = idx >> 10;
            const int b = idx & (BB - 1);
            const int n0 = chunk * (NN / NCHUNK);
            float m = -CUDART_INF_F, s = 0.f;
#pragma unroll 4
            for (int i = 0; i < NN / NCHUNK; i++) {
                const int n = n0 + i;
                const float x = __fmaf_rn(__ldg(root_logw + n), LOG2E,
                                          last[(size_t)n * BB + b]);
                const float mn = fmaxf(m, x);
                s = s * ex2(m - mn) + ex2(x - mn);
                m = mn;
            }
            g_partial[chunk * BB + b] = m + lg2(s);
        }
    }
    grid_sync();

    // ---------------- Phase 6: final combine (warp per column, ->nat log) -----
    {
        const int wgid = gtid >> 5;
        const int lane = gtid & 31;
        if (wgid < BB) {
            const int b = wgid;
            const float x0 = g_partial[lane * BB + b];
            const float x1 = g_partial[(lane + 32) * BB + b];
            float m = fmaxf(x0, x1);
#pragma unroll
            for (int o = 16; o > 0; o >>= 1)
                m = fmaxf(m, __shfl_xor_sync(0xFFFFFFFF, m, o));
            float s = ex2(x0 - m) + ex2(x1 - m);
#pragma unroll
            for (int o = 16; o > 0; o >>= 1)
                s += __shfl_xor_sync(0xFFFFFFFF, s, o);
            if (lane == 0) out[b] = (m + lg2(s)) * LN2;
        }
    }
}

// ---------------------------------------------------------------------------
extern "C" void kernel_launch(void* const* d_in, const int* in_sizes, int n_in,
                              void* d_out, int out_size) {
    const int*   inputs     = (const int*)  d_in[0];
    const float* input_logp = (const float*)d_in[1];
    const int*   prod_ids   = (const int*)  d_in[2];  // (L, E, 2)
    const int*   sum_ch_ids = (const int*)  d_in[3];  // (L, N, C)
    const float* sum_logw   = (const float*)d_in[4];  // (L, N, C)
    const float* root_logw  = (const float*)d_in[5];  // (N,)
    float* out = (float*)d_out;

    circuit_kernel<<<GRID_BLOCKS, THREADS>>>(
        inputs, input_logp,
        reinterpret_cast<const int2*>(prod_ids),
        sum_ch_ids,
        reinterpret_cast<const float4*>(sum_logw),
        root_logw, out);
}

// round 6
// speedup vs baseline: 1.6373x; 1.1370x over previous
#include <cuda_runtime.h>
#include <math_constants.h>

// Problem constants
#define NUM_VARS 64
#define KK       32
#define NUM_CATS 256
#define NUM_INPUT (NUM_VARS * KK)   // 2048
#define LL       4
#define EE       16384
#define NN       8192
#define CC       4
#define BB       1024
#define Q4       (BB / 4)           // 256 ushort4-groups per row
#define TOTAL_NODES (NUM_INPUT + LL * NN)  // 34816
#define NCHUNK   64

#define GRID_BLOCKS 740             // 5 blocks/SM on 148 SMs — co-resident
#define THREADS     256
#define NTHREADS    (GRID_BLOCKS * THREADS)

#define LOG2E 1.4426950408889634f
#define LN2   0.6931471805599453f
#define QSCALE   128.0f             // u16 = -v_log2 * 128, clamp 32767
#define INVQ     (1.0f / 128.0f)
#define MAGIC    8388608.0f         // 2^23
#define MAGIC_HI 0x4B000000u

// Node pool quantized to u16 (71.3 MB — fully L2-resident)
__device__ unsigned short g_node_q[(size_t)TOTAL_NODES * BB];
__device__ float g_partial[NCHUNK * BB];
__device__ uint2 g_pairs[LL * NN * CC];   // pre-scaled row offsets (row * Q4)

// Grid barrier
__device__ unsigned g_bar_count;
__device__ volatile unsigned g_bar_gen;

__device__ __forceinline__ void grid_sync() {
    __syncthreads();
    if (threadIdx.x == 0) {
        __threadfence();
        unsigned gen = g_bar_gen;
        if (atomicAdd(&g_bar_count, 1u) == GRID_BLOCKS - 1u) {
            g_bar_count = 0;
            __threadfence();
            g_bar_gen = gen + 1u;
        } else {
            while (g_bar_gen == gen) { }
        }
    }
    __syncthreads();
    __threadfence();
}

__device__ __forceinline__ float ex2(float x) {
    float r; asm("ex2.approx.ftz.f32 %0, %1;" : "=f"(r) : "f"(x)); return r;
}
__device__ __forceinline__ float lg2(float x) {
    float r; asm("lg2.approx.ftz.f32 %0, %1;" : "=f"(r) : "f"(x)); return r;
}

__device__ __forceinline__ float lse4_2(float a, float b, float c, float d) {
    float m = fmaxf(fmaxf(a, b), fmaxf(c, d));
    float s = ex2(a - m) + ex2(b - m) + ex2(c - m) + ex2(d - m);
    return m + lg2(s);
}

// decode lo/hi u16 of a packed pair-sum into x = w' - sum*INVQ
// w' = w_log2 + 65536*INVQ*... precomputed as wq = w_log2 + 65536.0f*INVQ? see below
__device__ __forceinline__ float dec_lo(unsigned s, float wq) {
    const float f = __uint_as_float((s & 0xFFFFu) | MAGIC_HI);  // sum + 2^23
    return fmaf(f, -INVQ, wq);
}
__device__ __forceinline__ float dec_hi(unsigned s, float wq) {
    const float f = __uint_as_float((s >> 16) | MAGIC_HI);
    return fmaf(f, -INVQ, wq);
}

__device__ __forceinline__ unsigned enc1(float v_log2) {
    // v_log2 <= 0; q = min(round(-v*128), 32767)
    unsigned q = __float2uint_rn(-v_log2 * QSCALE);   // F2I.U32 saturates at 0
    return umin(q, 32767u);
}

__global__ void __launch_bounds__(THREADS, 5)
circuit_kernel(const int* __restrict__ inputs,
               const float* __restrict__ input_logp,
               const int2* __restrict__ prod_ids,     // (L, E)
               const int* __restrict__ sum_ch_ids,    // (L, N, C)
               const float4* __restrict__ sum_logw,   // (L, N) as float4
               const float* __restrict__ root_logw,   // (N,)
               float* __restrict__ out) {
    const int gtid = blockIdx.x * THREADS + threadIdx.x;

    // ---------- Phase 0: input layer (quantize) + resolve (pre-scaled) --------
    for (int idx = gtid; idx < NUM_INPUT * BB; idx += NTHREADS) {
        const int v = idx >> 15;
        const int k = (idx >> 10) & (KK - 1);
        const int b = idx & (BB - 1);
        const int cat = __ldg(inputs + b * NUM_VARS + v);
        const float lp2 = __ldg(input_logp + ((v * KK + k) << 8) + cat) * LOG2E;
        g_node_q[idx] = (unsigned short)enc1(lp2);
    }
    for (int idx = gtid; idx < LL * NN * CC; idx += NTHREADS) {
        const int l = idx / (NN * CC);
        const int e = __ldg(sum_ch_ids + idx);
        const int2 p = __ldg(prod_ids + (size_t)l * EE + e);
        g_pairs[idx] = make_uint2((unsigned)p.x * Q4, (unsigned)p.y * Q4);
    }
    grid_sync();

    // ---------- Phases 1..4: sum layers (quantized gathers) -------------------
    const uint2* nq = reinterpret_cast<const uint2*>(g_node_q);  // 4 u16 per uint2
    uint2* nqo = reinterpret_cast<uint2*>(g_node_q);
    const unsigned c4 = threadIdx.x;   // ushort4-column 0..255

    for (int l = 0; l < LL; l++) {
        const int out_base = NUM_INPUT + l * NN;
        const uint4* prbase = reinterpret_cast<const uint4*>(g_pairs) + (size_t)l * NN * 2;
        const float4* lw = sum_logw + (size_t)l * NN;

        for (int n = blockIdx.x; n < NN; n += GRID_BLOCKS) {
            const uint4 pa = __ldg(prbase + n * 2);      // pre-scaled offsets
            const uint4 pb = __ldg(prbase + n * 2 + 1);
            const float4 w = __ldg(lw + n);
            // wq = w*LOG2E + 65536*INVQ*... : x = w2 - (f-2^23)*INVQ = (w2 + 2^23*INVQ) - f*INVQ
            const float wq0 = fmaf(w.x, LOG2E, MAGIC * INVQ);
            const float wq1 = fmaf(w.y, LOG2E, MAGIC * INVQ);
            const float wq2 = fmaf(w.z, LOG2E, MAGIC * INVQ);
            const float wq3 = fmaf(w.w, LOG2E, MAGIC * INVQ);

            const uint2 a0 = __ldg(nq + pa.x + c4);
            const uint2 q0 = __ldg(nq + pa.y + c4);
            const uint2 a1 = __ldg(nq + pa.z + c4);
            const uint2 q1 = __ldg(nq + pa.w + c4);
            const uint2 a2 = __ldg(nq + pb.x + c4);
            const uint2 q2 = __ldg(nq + pb.y + c4);
            const uint2 a3 = __ldg(nq + pb.z + c4);
            const uint2 q3 = __ldg(nq + pb.w + c4);

            // u16x2 SIMD pair-sums (values clamped <= 32767 -> no overflow)
            const unsigned s0x = __vadd2(a0.x, q0.x), s0y = __vadd2(a0.y, q0.y);
            const unsigned s1x = __vadd2(a1.x, q1.x), s1y = __vadd2(a1.y, q1.y);
            const unsigned s2x = __vadd2(a2.x, q2.x), s2y = __vadd2(a2.y, q2.y);
            const unsigned s3x = __vadd2(a3.x, q3.x), s3y = __vadd2(a3.y, q3.y);

            // 4 batch elements, lse over the 4 children each
            const float o0 = lse4_2(dec_lo(s0x, wq0), dec_lo(s1x, wq1),
                                    dec_lo(s2x, wq2), dec_lo(s3x, wq3));
            const float o1 = lse4_2(dec_hi(s0x, wq0), dec_hi(s1x, wq1),
                                    dec_hi(s2x, wq2), dec_hi(s3x, wq3));
            const float o2 = lse4_2(dec_lo(s0y, wq0), dec_lo(s1y, wq1),
                                    dec_lo(s2y, wq2), dec_lo(s3y, wq3));
            const float o3 = lse4_2(dec_hi(s0y, wq0), dec_hi(s1y, wq1),
                                    dec_hi(s2y, wq2), dec_hi(s3y, wq3));

            uint2 qo;
            qo.x = enc1(o0) | (enc1(o1) << 16);
            qo.y = enc1(o2) | (enc1(o3) << 16);
            nqo[(unsigned)(out_base + n) * Q4 + c4] = qo;
        }
        grid_sync();
    }

    // ---------- Phase 5: root partial logsumexp (decode u16) ------------------
    {
        const unsigned short* last = g_node_q + (size_t)(NUM_INPUT + (LL - 1) * NN) * BB;
        const int idx = gtid;
        if (idx < NCHUNK * BB) {
            const int chunk = idx >> 10;
            const int b = idx & (BB - 1);
            const int n0 = chunk * (NN / NCHUNK);
            float m = -CUDART_INF_F, s = 0.f;
#pragma unroll 4
            for (int i = 0; i < NN / NCHUNK; i++) {
                const int n = n0 + i;
                const float nv = -(float)last[(unsigned)n * BB + b] * INVQ;
                const float x = fmaf(__ldg(root_logw + n), LOG2E, nv);
                const float mn = fmaxf(m, x);
                s = s * ex2(m - mn) + ex2(x - mn);
                m = mn;
            }
            g_partial[chunk * BB + b] = m + lg2(s);
        }
    }
    grid_sync();

    // ---------- Phase 6: final combine (-> natural log) -----------------------
    {
        const int wgid = gtid >> 5;
        const int lane = gtid & 31;
        if (wgid < BB) {
            const int b = wgid;
            const float x0 = g_partial[lane * BB + b];
            const float x1 = g_partial[(lane + 32) * BB + b];
            float m = fmaxf(x0, x1);
#pragma unroll
            for (int o = 16; o > 0; o >>= 1)
                m = fmaxf(m, __shfl_xor_sync(0xFFFFFFFF, m, o));
            float s = ex2(x0 - m) + ex2(x1 - m);
#pragma unroll
            for (int o = 16; o > 0; o >>= 1)
                s += __shfl_xor_sync(0xFFFFFFFF, s, o);
            if (lane == 0) out[b] = (m + lg2(s)) * LN2;
        }
    }
}

// ---------------------------------------------------------------------------
extern "C" void kernel_launch(void* const* d_in, const int* in_sizes, int n_in,
                              void* d_out, int out_size) {
    const int*   inputs     = (const int*)  d_in[0];
    const float* input_logp = (const float*)d_in[1];
    const int*   prod_ids   = (const int*)  d_in[2];  // (L, E, 2)
    const int*   sum_ch_ids = (const int*)  d_in[3];  // (L, N, C)
    const float* sum_logw   = (const float*)d_in[4];  // (L, N, C)
    const float* root_logw  = (const float*)d_in[5];  // (N,)
    float* out = (float*)d_out;

    circuit_kernel<<<GRID_BLOCKS, THREADS>>>(
        inputs, input_logp,
        reinterpret_cast<const int2*>(prod_ids),
        sum_ch_ids,
        reinterpret_cast<const float4*>(sum_logw),
        root_logw, out);
}